// round 6
// baseline (speedup 1.0000x reference)
#include <cuda_runtime.h>
#include <cuda_fp16.h>
#include <cstdint>

// GCN layer: out = D^-1/2 A D^-1/2 (X W + b)
// N=100000 nodes, E=1600000 edges, D_IN=256, D_OUT=128
//
// R6: shuffle-batched SpMM — one coalesced epack load per 32 edges, (col,w)
//     broadcast via shfl, making all support loads in a batch independent
//     (MLP ~32 instead of 2-chain). Everything else unchanged from R5.

#define N_NODES 100000
#define N_EDGES 1600000
#define D_IN    256
#define D_OUT   128

#define SCAN_BS 1024
#define N_SCAN_BLOCKS ((N_NODES + SCAN_BS - 1) / SCAN_BS)   // 98

// ---- scratch (static device memory) ----
__device__ float  g_deg[N_NODES];
__device__ float  g_dinv[N_NODES];
__device__ int    g_cnt[N_NODES];
__device__ int    g_rowstart[N_NODES + 1];   // per-block partial exclusive scan
__device__ int    g_blocksum[N_SCAN_BLOCKS];
__device__ int    g_blockoff[N_SCAN_BLOCKS];
__device__ int    g_ticket;
__device__ int    g_pos[N_EDGES];            // within-row position of each edge
__device__ __half g_support_h[(size_t)N_NODES * D_OUT];  // 25.6 MB (L2-resident)
__device__ int2   g_epack[N_EDGES];          // {col, vals-as-int}

// ---------------------------------------------------------------- init
__global__ void k_init() {
    int i = blockIdx.x * blockDim.x + threadIdx.x;
    if (i < N_NODES) {
        g_deg[i] = 0.0f;
        g_cnt[i] = 0;
    }
    if (i == 0) g_ticket = 0;
}

// ---------------------- degree/count + within-row position assignment
__global__ void k_deg_count(const int* __restrict__ row,
                            const float* __restrict__ vals) {
    int e = blockIdx.x * blockDim.x + threadIdx.x;
    if (e < N_EDGES) {
        int r = row[e];
        atomicAdd(&g_deg[r], vals[e]);
        g_pos[e] = atomicAdd(&g_cnt[r], 1);   // coalesced store of position
    }
}

// ---- scan stage 1 (per block) + fused d^-1/2 + fused stage-2 (last block)
__global__ void k_scan1() {
    __shared__ int warp_sums[32];
    __shared__ int sh_blocksum;
    __shared__ int sh_islast;
    int b = blockIdx.x, t = threadIdx.x;
    int i = b * SCAN_BS + t;
    int v = (i < N_NODES) ? g_cnt[i] : 0;

    if (i < N_NODES) {
        float d = g_deg[i];
        g_dinv[i] = (d > 0.0f) ? rsqrtf(fmaxf(d, 1e-12f)) : 0.0f;
    }

    int x = v;
    #pragma unroll
    for (int o = 1; o < 32; o <<= 1) {
        int y = __shfl_up_sync(0xFFFFFFFFu, x, o);
        if ((t & 31) >= o) x += y;
    }
    if ((t & 31) == 31) warp_sums[t >> 5] = x;
    __syncthreads();
    if (t < 32) {
        int s = warp_sums[t];
        #pragma unroll
        for (int o = 1; o < 32; o <<= 1) {
            int y = __shfl_up_sync(0xFFFFFFFFu, s, o);
            if (t >= o) s += y;
        }
        warp_sums[t] = s;
    }
    __syncthreads();
    int warp_off = (t >= 32) ? warp_sums[(t >> 5) - 1] : 0;
    int excl = x - v + warp_off;
    if (i < N_NODES) g_rowstart[i] = excl;
    if (t == SCAN_BS - 1) sh_blocksum = excl + v;
    __syncthreads();

    if (t == 0) {
        g_blocksum[b] = sh_blocksum;
        __threadfence();
        sh_islast = (atomicAdd(&g_ticket, 1) == gridDim.x - 1);
    }
    __syncthreads();

    if (sh_islast && t < 32) {
        int carry = 0;
        #pragma unroll
        for (int chunk = 0; chunk < (N_SCAN_BLOCKS + 31) / 32; chunk++) {
            int idx = chunk * 32 + t;
            int bv = (idx < N_SCAN_BLOCKS) ? g_blocksum[idx] : 0;
            int xx = bv;
            #pragma unroll
            for (int o = 1; o < 32; o <<= 1) {
                int y = __shfl_up_sync(0xFFFFFFFFu, xx, o);
                if (t >= o) xx += y;
            }
            int incl = xx + carry;
            if (idx < N_SCAN_BLOCKS) g_blockoff[idx] = incl - bv;
            carry = __shfl_sync(0xFFFFFFFFu, incl, 31);
        }
        if (t == 0) g_rowstart[N_NODES] = carry;
    }
}

// -------------------------------------------------- bucket (atomic-free)
__global__ void k_bucket(const int* __restrict__ row,
                         const int* __restrict__ col,
                         const float* __restrict__ vals) {
    int e = blockIdx.x * blockDim.x + threadIdx.x;
    if (e < N_EDGES) {
        int r = row[e];
        int pos = g_rowstart[r] + g_blockoff[r >> 10] + g_pos[e];
        g_epack[pos] = make_int2(col[e], __float_as_int(vals[e]));
    }
}

// ------------------------------------------------------------------ GEMM
// support' = dinv[row] * (X[N,256] @ W[256,128] + b)  via tf32 mma m16n8k8.
#define GBM 128
#define GBK 32
#define AS_STRIDE 36
#define BS_STRIDE 136

__device__ __forceinline__ uint32_t f2tf32(float f) {
    uint32_t r;
    asm("cvt.rna.tf32.f32 %0, %1;" : "=r"(r) : "f"(f));
    return r;
}

__device__ __forceinline__ void mma_tf32(float* c, const uint32_t* a, const uint32_t* b) {
    asm("mma.sync.aligned.m16n8k8.row.col.f32.tf32.tf32.f32 "
        "{%0,%1,%2,%3}, {%4,%5,%6,%7}, {%8,%9}, {%0,%1,%2,%3};"
        : "+f"(c[0]), "+f"(c[1]), "+f"(c[2]), "+f"(c[3])
        : "r"(a[0]), "r"(a[1]), "r"(a[2]), "r"(a[3]), "r"(b[0]), "r"(b[1]));
}

__global__ __launch_bounds__(256) void k_gemm_mma(const float* __restrict__ x,
                                                  const float* __restrict__ W,
                                                  const float* __restrict__ bias) {
    __shared__ uint32_t as[GBM * AS_STRIDE];
    __shared__ uint32_t bs[GBK * BS_STRIDE];

    int tid  = threadIdx.x;
    int wid  = tid >> 5, lane = tid & 31;
    int g    = lane >> 2, tc = lane & 3;
    int wm   = wid >> 2, wn = wid & 3;
    int row0 = blockIdx.x * GBM;

    float acc[4][4][4];
    #pragma unroll
    for (int mi = 0; mi < 4; mi++)
        #pragma unroll
        for (int ni = 0; ni < 4; ni++)
            #pragma unroll
            for (int q = 0; q < 4; q++) acc[mi][ni][q] = 0.0f;

    int a_r = tid >> 3;
    int a_c = (tid & 7) * 4;
    int b_r = tid >> 5;
    int b_c = (tid & 31) * 4;

    for (int k0 = 0; k0 < D_IN; k0 += GBK) {
        #pragma unroll
        for (int p = 0; p < 4; p++) {
            int m = a_r + 32 * p;
            int r = row0 + m;
            float4 v = (r < N_NODES)
                ? *(const float4*)(x + (size_t)r * D_IN + k0 + a_c)
                : make_float4(0.f, 0.f, 0.f, 0.f);
            uint32_t* d = &as[m * AS_STRIDE + a_c];
            d[0] = f2tf32(v.x); d[1] = f2tf32(v.y);
            d[2] = f2tf32(v.z); d[3] = f2tf32(v.w);
        }
        #pragma unroll
        for (int p = 0; p < 4; p++) {
            int k = b_r + 8 * p;
            float4 v = *(const float4*)(W + (size_t)(k0 + k) * D_OUT + b_c);
            uint32_t* d = &bs[k * BS_STRIDE + b_c];
            d[0] = f2tf32(v.x); d[1] = f2tf32(v.y);
            d[2] = f2tf32(v.z); d[3] = f2tf32(v.w);
        }
        __syncthreads();

        #pragma unroll
        for (int k8 = 0; k8 < 4; k8++) {
            uint32_t af[4][4], bf[4][2];
            #pragma unroll
            for (int mi = 0; mi < 4; mi++) {
                const uint32_t* pa = &as[(wm * 64 + mi * 16 + g) * AS_STRIDE + k8 * 8 + tc];
                af[mi][0] = pa[0];
                af[mi][1] = pa[8 * AS_STRIDE];
                af[mi][2] = pa[4];
                af[mi][3] = pa[8 * AS_STRIDE + 4];
            }
            #pragma unroll
            for (int ni = 0; ni < 4; ni++) {
                const uint32_t* pb = &bs[(k8 * 8 + tc) * BS_STRIDE + wn * 32 + ni * 8 + g];
                bf[ni][0] = pb[0];
                bf[ni][1] = pb[4 * BS_STRIDE];
            }
            #pragma unroll
            for (int mi = 0; mi < 4; mi++)
                #pragma unroll
                for (int ni = 0; ni < 4; ni++)
                    mma_tf32(acc[mi][ni], af[mi], bf[ni]);
        }
        __syncthreads();
    }

    // epilogue: (acc + bias) * dinv[row], convert fp16, store half2
    #pragma unroll
    for (int ni = 0; ni < 4; ni++) {
        int c = wn * 32 + ni * 8 + 2 * tc;
        float b0 = __ldg(bias + c);
        float b1 = __ldg(bias + c + 1);
        #pragma unroll
        for (int mi = 0; mi < 4; mi++) {
            int r = row0 + wm * 64 + mi * 16 + g;
            if (r < N_NODES) {
                float d0 = g_dinv[r];
                __half2 h = __floats2half2_rn((acc[mi][ni][0] + b0) * d0,
                                              (acc[mi][ni][1] + b1) * d0);
                *(__half2*)(g_support_h + (size_t)r * D_OUT + c) = h;
            }
            if (r + 8 < N_NODES) {
                float d1 = g_dinv[r + 8];
                __half2 h = __floats2half2_rn((acc[mi][ni][2] + b0) * d1,
                                              (acc[mi][ni][3] + b1) * d1);
                *(__half2*)(g_support_h + (size_t)(r + 8) * D_OUT + c) = h;
            }
        }
    }
}

// ------------------------------------------------------------------ SpMM
// One warp per destination row, shuffle-batched: lane L loads epack[base+L]
// (one coalesced LDG.64 per 32 edges), then (col,w) broadcast via shfl.
// All support loads within a batch are address-independent -> deep MLP.
__global__ __launch_bounds__(256) void k_spmm(float* __restrict__ out) {
    int w = (blockIdx.x * blockDim.x + threadIdx.x) >> 5;
    int lane = threadIdx.x & 31;
    if (w >= N_NODES) return;

    int e0 = g_rowstart[w] + g_blockoff[w >> 10];
    int e1 = (w + 1 < N_NODES) ? (g_rowstart[w + 1] + g_blockoff[(w + 1) >> 10])
                               : g_rowstart[N_NODES];

    float4 acc = make_float4(0.f, 0.f, 0.f, 0.f);

    for (int base = e0; base < e1; base += 32) {
        int n = e1 - base;
        if (n > 32) n = 32;
        int2 p = (base + lane < e1) ? __ldg(&g_epack[base + lane])
                                    : make_int2(0, 0);
        #pragma unroll 4
        for (int k = 0; k < n; k++) {
            int   c  = __shfl_sync(0xFFFFFFFFu, p.x, k);
            float wt = __int_as_float(__shfl_sync(0xFFFFFFFFu, p.y, k));
            uint2 u  = __ldg(((const uint2*)(g_support_h + (size_t)c * D_OUT)) + lane);
            float2 f0 = __half22float2(*(const __half2*)&u.x);
            float2 f1 = __half22float2(*(const __half2*)&u.y);
            acc.x += wt * f0.x;
            acc.y += wt * f0.y;
            acc.z += wt * f1.x;
            acc.w += wt * f1.y;
        }
    }

    float dr = __ldg(&g_dinv[w]);
    acc.x *= dr; acc.y *= dr; acc.z *= dr; acc.w *= dr;
    ((float4*)(out + (size_t)w * D_OUT))[lane] = acc;
}

// ------------------------------------------------------------- launcher
extern "C" void kernel_launch(void* const* d_in, const int* in_sizes, int n_in,
                              void* d_out, int out_size) {
    const float* x    = (const float*)d_in[0];
    const int*   row  = (const int*)  d_in[1];
    const int*   col  = (const int*)  d_in[2];
    const float* vals = (const float*)d_in[3];
    const float* W    = (const float*)d_in[4];
    const float* bias = (const float*)d_in[5];
    float* out = (float*)d_out;

    (void)in_sizes; (void)n_in; (void)out_size;

    const int TB = 256;
    k_init     <<<(N_NODES + TB - 1) / TB, TB>>>();
    k_deg_count<<<(N_EDGES + TB - 1) / TB, TB>>>(row, vals);
    k_scan1    <<<N_SCAN_BLOCKS, SCAN_BS>>>();
    k_bucket   <<<(N_EDGES + TB - 1) / TB, TB>>>(row, col, vals);
    k_gemm_mma <<<(N_NODES + GBM - 1) / GBM, 256>>>(x, W, bias);
    k_spmm     <<<(N_NODES * 32 + TB - 1) / TB, TB>>>(out);
}

// round 7
// speedup vs baseline: 1.0560x; 1.0560x over previous
#include <cuda_runtime.h>
#include <cuda_fp16.h>
#include <cstdint>

// GCN layer: out = D^-1/2 A D^-1/2 (X W + b)
// N=100000 nodes, E=1600000 edges, D_IN=256, D_OUT=128
//
// R7: SpMM reverted to R5 loop (R6 shuffle variant measured slower).
//     GEMM software-pipelined: next X tile prefetched into registers during
//     MMA compute. gemm moved to launch slot #4 (independent of bucket) so
//     the fixed ncu window finally profiles it.

#define N_NODES 100000
#define N_EDGES 1600000
#define D_IN    256
#define D_OUT   128

#define SCAN_BS 1024
#define N_SCAN_BLOCKS ((N_NODES + SCAN_BS - 1) / SCAN_BS)   // 98

// ---- scratch (static device memory) ----
__device__ float  g_deg[N_NODES];
__device__ float  g_dinv[N_NODES];
__device__ int    g_cnt[N_NODES];
__device__ int    g_rowstart[N_NODES + 1];
__device__ int    g_blocksum[N_SCAN_BLOCKS];
__device__ int    g_blockoff[N_SCAN_BLOCKS];
__device__ int    g_ticket;
__device__ int    g_pos[N_EDGES];
__device__ __half g_support_h[(size_t)N_NODES * D_OUT];  // 25.6 MB (L2-resident)
__device__ int2   g_epack[N_EDGES];                      // {col, vals-as-int}

// ---------------------------------------------------------------- init
__global__ void k_init() {
    int i = blockIdx.x * blockDim.x + threadIdx.x;
    if (i < N_NODES) {
        g_deg[i] = 0.0f;
        g_cnt[i] = 0;
    }
    if (i == 0) g_ticket = 0;
}

// ---------------------- degree/count + within-row position assignment
__global__ void k_deg_count(const int* __restrict__ row,
                            const float* __restrict__ vals) {
    int e = blockIdx.x * blockDim.x + threadIdx.x;
    if (e < N_EDGES) {
        int r = row[e];
        atomicAdd(&g_deg[r], vals[e]);
        g_pos[e] = atomicAdd(&g_cnt[r], 1);
    }
}

// ---- scan stage 1 (per block) + fused d^-1/2 + fused stage-2 (last block)
__global__ void k_scan1() {
    __shared__ int warp_sums[32];
    __shared__ int sh_blocksum;
    __shared__ int sh_islast;
    int b = blockIdx.x, t = threadIdx.x;
    int i = b * SCAN_BS + t;
    int v = (i < N_NODES) ? g_cnt[i] : 0;

    if (i < N_NODES) {
        float d = g_deg[i];
        g_dinv[i] = (d > 0.0f) ? rsqrtf(fmaxf(d, 1e-12f)) : 0.0f;
    }

    int x = v;
    #pragma unroll
    for (int o = 1; o < 32; o <<= 1) {
        int y = __shfl_up_sync(0xFFFFFFFFu, x, o);
        if ((t & 31) >= o) x += y;
    }
    if ((t & 31) == 31) warp_sums[t >> 5] = x;
    __syncthreads();
    if (t < 32) {
        int s = warp_sums[t];
        #pragma unroll
        for (int o = 1; o < 32; o <<= 1) {
            int y = __shfl_up_sync(0xFFFFFFFFu, s, o);
            if (t >= o) s += y;
        }
        warp_sums[t] = s;
    }
    __syncthreads();
    int warp_off = (t >= 32) ? warp_sums[(t >> 5) - 1] : 0;
    int excl = x - v + warp_off;
    if (i < N_NODES) g_rowstart[i] = excl;
    if (t == SCAN_BS - 1) sh_blocksum = excl + v;
    __syncthreads();

    if (t == 0) {
        g_blocksum[b] = sh_blocksum;
        __threadfence();
        sh_islast = (atomicAdd(&g_ticket, 1) == gridDim.x - 1);
    }
    __syncthreads();

    if (sh_islast && t < 32) {
        int carry = 0;
        #pragma unroll
        for (int chunk = 0; chunk < (N_SCAN_BLOCKS + 31) / 32; chunk++) {
            int idx = chunk * 32 + t;
            int bv = (idx < N_SCAN_BLOCKS) ? g_blocksum[idx] : 0;
            int xx = bv;
            #pragma unroll
            for (int o = 1; o < 32; o <<= 1) {
                int y = __shfl_up_sync(0xFFFFFFFFu, xx, o);
                if (t >= o) xx += y;
            }
            int incl = xx + carry;
            if (idx < N_SCAN_BLOCKS) g_blockoff[idx] = incl - bv;
            carry = __shfl_sync(0xFFFFFFFFu, incl, 31);
        }
        if (t == 0) g_rowstart[N_NODES] = carry;
    }
}

// -------------------------------------------------- bucket (atomic-free)
__global__ void k_bucket(const int* __restrict__ row,
                         const int* __restrict__ col,
                         const float* __restrict__ vals) {
    int e = blockIdx.x * blockDim.x + threadIdx.x;
    if (e < N_EDGES) {
        int r = row[e];
        int pos = g_rowstart[r] + g_blockoff[r >> 10] + g_pos[e];
        g_epack[pos] = make_int2(col[e], __float_as_int(vals[e]));
    }
}

// ------------------------------------------------------------------ GEMM
// support' = dinv[row] * (X[N,256] @ W[256,128] + b)  via tf32 mma m16n8k8.
// Software-pipelined: X tile for k0+1 prefetched into regs during MMA of k0.
#define GBM 128
#define GBK 32
#define AS_STRIDE 36
#define BS_STRIDE 136

__device__ __forceinline__ uint32_t f2tf32(float f) {
    uint32_t r;
    asm("cvt.rna.tf32.f32 %0, %1;" : "=r"(r) : "f"(f));
    return r;
}

__device__ __forceinline__ void mma_tf32(float* c, const uint32_t* a, const uint32_t* b) {
    asm("mma.sync.aligned.m16n8k8.row.col.f32.tf32.tf32.f32 "
        "{%0,%1,%2,%3}, {%4,%5,%6,%7}, {%8,%9}, {%0,%1,%2,%3};"
        : "+f"(c[0]), "+f"(c[1]), "+f"(c[2]), "+f"(c[3])
        : "r"(a[0]), "r"(a[1]), "r"(a[2]), "r"(a[3]), "r"(b[0]), "r"(b[1]));
}

__global__ __launch_bounds__(256) void k_gemm_mma(const float* __restrict__ x,
                                                  const float* __restrict__ W,
                                                  const float* __restrict__ bias) {
    __shared__ uint32_t as[GBM * AS_STRIDE];
    __shared__ uint32_t bs[GBK * BS_STRIDE];

    int tid  = threadIdx.x;
    int wid  = tid >> 5, lane = tid & 31;
    int g    = lane >> 2, tc = lane & 3;
    int wm   = wid >> 2, wn = wid & 3;
    int row0 = blockIdx.x * GBM;

    float acc[4][4][4];
    #pragma unroll
    for (int mi = 0; mi < 4; mi++)
        #pragma unroll
        for (int ni = 0; ni < 4; ni++)
            #pragma unroll
            for (int q = 0; q < 4; q++) acc[mi][ni][q] = 0.0f;

    int a_r = tid >> 3;
    int a_c = (tid & 7) * 4;
    int b_r = tid >> 5;
    int b_c = (tid & 31) * 4;

    // prologue: load first X tile into regs
    float4 xa[4];
    #pragma unroll
    for (int p = 0; p < 4; p++) {
        int r = row0 + a_r + 32 * p;
        xa[p] = (r < N_NODES)
            ? *(const float4*)(x + (size_t)r * D_IN + 0 + a_c)
            : make_float4(0.f, 0.f, 0.f, 0.f);
    }

    for (int k0 = 0; k0 < D_IN; k0 += GBK) {
        // store current X tile (regs -> smem, with RNA cvt)
        #pragma unroll
        for (int p = 0; p < 4; p++) {
            int m = a_r + 32 * p;
            uint32_t* d = &as[m * AS_STRIDE + a_c];
            d[0] = f2tf32(xa[p].x); d[1] = f2tf32(xa[p].y);
            d[2] = f2tf32(xa[p].z); d[3] = f2tf32(xa[p].w);
        }
        // W tile (L2-hot after first wave; not pipelined)
        #pragma unroll
        for (int p = 0; p < 4; p++) {
            int k = b_r + 8 * p;
            float4 v = *(const float4*)(W + (size_t)(k0 + k) * D_OUT + b_c);
            uint32_t* d = &bs[k * BS_STRIDE + b_c];
            d[0] = f2tf32(v.x); d[1] = f2tf32(v.y);
            d[2] = f2tf32(v.z); d[3] = f2tf32(v.w);
        }
        __syncthreads();

        // prefetch next X tile (LDGs overlap with MMA below)
        if (k0 + GBK < D_IN) {
            #pragma unroll
            for (int p = 0; p < 4; p++) {
                int r = row0 + a_r + 32 * p;
                xa[p] = (r < N_NODES)
                    ? *(const float4*)(x + (size_t)r * D_IN + (k0 + GBK) + a_c)
                    : make_float4(0.f, 0.f, 0.f, 0.f);
            }
        }

        #pragma unroll
        for (int k8 = 0; k8 < 4; k8++) {
            uint32_t af[4][4], bf[4][2];
            #pragma unroll
            for (int mi = 0; mi < 4; mi++) {
                const uint32_t* pa = &as[(wm * 64 + mi * 16 + g) * AS_STRIDE + k8 * 8 + tc];
                af[mi][0] = pa[0];
                af[mi][1] = pa[8 * AS_STRIDE];
                af[mi][2] = pa[4];
                af[mi][3] = pa[8 * AS_STRIDE + 4];
            }
            #pragma unroll
            for (int ni = 0; ni < 4; ni++) {
                const uint32_t* pb = &bs[(k8 * 8 + tc) * BS_STRIDE + wn * 32 + ni * 8 + g];
                bf[ni][0] = pb[0];
                bf[ni][1] = pb[4 * BS_STRIDE];
            }
            #pragma unroll
            for (int mi = 0; mi < 4; mi++)
                #pragma unroll
                for (int ni = 0; ni < 4; ni++)
                    mma_tf32(acc[mi][ni], af[mi], bf[ni]);
        }
        __syncthreads();
    }

    // epilogue: (acc + bias) * dinv[row], convert fp16, store half2
    #pragma unroll
    for (int ni = 0; ni < 4; ni++) {
        int c = wn * 32 + ni * 8 + 2 * tc;
        float b0 = __ldg(bias + c);
        float b1 = __ldg(bias + c + 1);
        #pragma unroll
        for (int mi = 0; mi < 4; mi++) {
            int r = row0 + wm * 64 + mi * 16 + g;
            if (r < N_NODES) {
                float d0 = g_dinv[r];
                __half2 h = __floats2half2_rn((acc[mi][ni][0] + b0) * d0,
                                              (acc[mi][ni][1] + b1) * d0);
                *(__half2*)(g_support_h + (size_t)r * D_OUT + c) = h;
            }
            if (r + 8 < N_NODES) {
                float d1 = g_dinv[r + 8];
                __half2 h = __floats2half2_rn((acc[mi][ni][2] + b0) * d1,
                                              (acc[mi][ni][3] + b1) * d1);
                *(__half2*)(g_support_h + (size_t)(r + 8) * D_OUT + c) = h;
            }
        }
    }
}

// ------------------------------------------------------------------ SpMM
// One warp per destination row (R5 form — measured fastest); dinv[row] scale.
__global__ __launch_bounds__(256) void k_spmm(float* __restrict__ out) {
    int w = (blockIdx.x * blockDim.x + threadIdx.x) >> 5;
    int lane = threadIdx.x & 31;
    if (w >= N_NODES) return;

    int e0 = g_rowstart[w] + g_blockoff[w >> 10];
    int e1 = (w + 1 < N_NODES) ? (g_rowstart[w + 1] + g_blockoff[(w + 1) >> 10])
                               : g_rowstart[N_NODES];

    float4 acc = make_float4(0.f, 0.f, 0.f, 0.f);
    #pragma unroll 4
    for (int e = e0; e < e1; e++) {
        int2  p  = __ldg(&g_epack[e]);
        int   c  = p.x;
        float wt = __int_as_float(p.y);
        uint2 u  = __ldg(((const uint2*)(g_support_h + (size_t)c * D_OUT)) + lane);
        float2 f0 = __half22float2(*(const __half2*)&u.x);
        float2 f1 = __half22float2(*(const __half2*)&u.y);
        acc.x += wt * f0.x;
        acc.y += wt * f0.y;
        acc.z += wt * f1.x;
        acc.w += wt * f1.y;
    }

    float dr = __ldg(&g_dinv[w]);
    acc.x *= dr; acc.y *= dr; acc.z *= dr; acc.w *= dr;
    ((float4*)(out + (size_t)w * D_OUT))[lane] = acc;
}

// ------------------------------------------------------------- launcher
// gemm placed at slot #4 (independent of bucket) so ncu's fixed window
// profiles it instead of bucket.
extern "C" void kernel_launch(void* const* d_in, const int* in_sizes, int n_in,
                              void* d_out, int out_size) {
    const float* x    = (const float*)d_in[0];
    const int*   row  = (const int*)  d_in[1];
    const int*   col  = (const int*)  d_in[2];
    const float* vals = (const float*)d_in[3];
    const float* W    = (const float*)d_in[4];
    const float* bias = (const float*)d_in[5];
    float* out = (float*)d_out;

    (void)in_sizes; (void)n_in; (void)out_size;

    const int TB = 256;
    k_init     <<<(N_NODES + TB - 1) / TB, TB>>>();
    k_deg_count<<<(N_EDGES + TB - 1) / TB, TB>>>(row, vals);
    k_scan1    <<<N_SCAN_BLOCKS, SCAN_BS>>>();
    k_gemm_mma <<<(N_NODES + GBM - 1) / GBM, 256>>>(x, W, bias);   // slot #4
    k_bucket   <<<(N_EDGES + TB - 1) / TB, TB>>>(row, col, vals);
    k_spmm     <<<(N_NODES * 32 + TB - 1) / TB, TB>>>(out);
}